// round 14
// baseline (speedup 1.0000x reference)
#include <cuda_runtime.h>
#include <cuda_bf16.h>
#include <stdint.h>
#include <math.h>

#define ZB   16
#define ZD   256
#define ZT   4096
#define NVEC (ZB*ZT)            // 65536
#define NELEM (ZB*ZD*ZT)        // 16777216
#define NCODE 1024

#define TILE_M 64
#define TILE_N 128
#define BK     32
#define NT_TILES (NCODE/TILE_N)   // 8
#define KCH      (ZD/BK)          // 8
#define NITER    (NT_TILES*KCH)   // 64
#define THREADS  256

// A hi+lo: row stride 264 bf16 = 528 B
#define STRA_B 528
#define A_H_OFF 0
#define A_L_OFF (TILE_M*STRA_B)            // 33792
#define B_BASE (2*TILE_M*STRA_B)           // 67584
// B chunk: 128 rows x 80B, hi+lo, double buffered
#define STRB_B 80
#define B_HL   (TILE_N*STRB_B)             // 10240
#define B_BUF  (2*B_HL)                    // 20480
#define SMEM_TOTAL (B_BASE + 2*B_BUF)      // 108544
// epilogue scratch overlaps B region (B dead by then)
#define STD    B_BASE                      // [row][wn] float
#define STI    (B_BASE + TILE_M*4*4)       // +1024

// ---------------- scratch --------------------------------------------------
__device__ __align__(16) __nv_bfloat16 g_eh[NCODE*ZD];
__device__ __align__(16) __nv_bfloat16 g_el[NCODE*ZD];
__device__ int           g_idx[NVEC];
__device__ unsigned int  g_hist[NCODE];
__device__ float         g_enorm[NCODE];
__device__ double        g_loss;

// ---------------- helpers --------------------------------------------------
__device__ __forceinline__ void mma_bf16(float c[4], uint32_t a0, uint32_t a1,
                                         uint32_t a2, uint32_t a3,
                                         uint32_t b0, uint32_t b1) {
    asm volatile(
        "mma.sync.aligned.m16n8k16.row.col.f32.bf16.bf16.f32 "
        "{%0,%1,%2,%3}, {%4,%5,%6,%7}, {%8,%9}, {%0,%1,%2,%3};"
        : "+f"(c[0]), "+f"(c[1]), "+f"(c[2]), "+f"(c[3])
        : "r"(a0), "r"(a1), "r"(a2), "r"(a3), "r"(b0), "r"(b1));
}
#define LDSM_X4(r0, r1, r2, r3, addr) \
    asm volatile("ldmatrix.sync.aligned.m8n8.x4.shared.b16 {%0,%1,%2,%3}, [%4];" \
        : "=r"(r0), "=r"(r1), "=r"(r2), "=r"(r3) : "r"(addr))
#define CP_ASYNC16(dst, src) \
    asm volatile("cp.async.cg.shared.global [%0], [%1], 16;" :: "r"(dst), "l"(src))
#define CP_COMMIT() asm volatile("cp.async.commit_group;" ::: "memory")
#define CP_WAIT1()  asm volatile("cp.async.wait_group 1;" ::: "memory")

__device__ __forceinline__ uint32_t smem_u32(const void* p) {
    uint32_t a;
    asm("{ .reg .u64 t; cvta.to.shared.u64 t, %1; cvt.u32.u64 %0, t; }" : "=r"(a) : "l"(p));
    return a;
}

// ---------------- kernel 1: init + codebook prep ---------------------------
__global__ __launch_bounds__(256) void vq_embprep(const float* __restrict__ emb) {
    int c = blockIdx.x, d = threadIdx.x;
    if (d == 0) {
        g_hist[c] = 0u;
        if (c == 0) g_loss = 0.0;
    }
    float v = emb[(size_t)c * ZD + d];
    __nv_bfloat16 h = __float2bfloat16_rn(v);
    float hf = __bfloat162float(h);
    g_eh[(size_t)c * ZD + d] = h;
    g_el[(size_t)c * ZD + d] = __float2bfloat16_rn(v - hf);

    float sv = v * v;
    __shared__ float wv[8];
    int lane = d & 31, w = d >> 5;
    #pragma unroll
    for (int o = 16; o > 0; o >>= 1) sv += __shfl_down_sync(0xffffffffu, sv, o);
    if (lane == 0) wv[w] = sv;
    __syncthreads();
    if (d == 0) {
        float tv = 0.f;
        #pragma unroll
        for (int i = 0; i < 8; i++) tv += wv[i];
        g_enorm[c] = tv;
    }
}

// ---------------- kernel 2: 3-pass HMMA exact argmin (ldmatrix) ------------
extern __shared__ char smem[];

__device__ __forceinline__ void prefetch_chunk(int it2, int tid) {
    int nt = it2 >> 3, kc = it2 & 7, buf = it2 & 1;
    #pragma unroll
    for (int q = 0; q < 4; q++) {
        int idx = tid + q * THREADS;        // 0..1023
        int hl  = idx >> 9;
        int rem = idx & 511;
        int row = rem >> 2;
        int seg = rem & 3;
        const __nv_bfloat16* src =
            (hl ? g_el : g_eh) + ((size_t)(nt * TILE_N + row) * ZD + kc * BK + seg * 8);
        uint32_t dst = smem_u32(smem) + B_BASE + buf * B_BUF + hl * B_HL
                     + row * STRB_B + seg * 16;
        CP_ASYNC16(dst, src);
    }
}

__global__ __launch_bounds__(THREADS, 2)
void vq_argmin_3p(const float* __restrict__ z) {
    int tid = threadIdx.x, lane = tid & 31, wid = tid >> 5;
    int g = lane >> 2, t4 = lane & 3;
    int wm = wid & 1, wn = wid >> 1;
    int l15 = lane & 15;
    uint32_t hi16 = (lane & 16) ? 16u : 0u;

    int n0 = blockIdx.x * TILE_M;
    int b  = n0 / ZT, t0 = n0 % ZT;
    const float* zb = z + (size_t)b * ZD * ZT + t0;
    uint32_t sbA = smem_u32(smem);

    // A tile: hi + lo split (64 rows x 256 dims)
    {
        int r = tid & 63;
        #pragma unroll 1
        for (int itl = 0; itl < 8; itl++) {
            int kq = (tid >> 6) + itl * 4;       // 0..31
            union { __nv_bfloat16 h[8]; uint4 u; } H, L;
            #pragma unroll
            for (int j = 0; j < 8; j++) {
                float v = zb[(size_t)(kq * 8 + j) * ZT + r];
                __nv_bfloat16 hh = __float2bfloat16_rn(v);
                H.h[j] = hh;
                L.h[j] = __float2bfloat16_rn(v - __bfloat162float(hh));
            }
            uint32_t off = (uint32_t)(r * STRA_B + kq * 16);
            *(uint4*)(smem + A_H_OFF + off) = H.u;
            *(uint4*)(smem + A_L_OFF + off) = L.u;
        }
    }

    prefetch_chunk(0, tid);
    CP_COMMIT();
    __syncthreads();

    // precomputed ldmatrix lane addresses (loop-invariant parts)
    uint32_t aAddrH[2], aAddrL[2], bOff[2];
    #pragma unroll
    for (int i = 0; i < 2; i++) {
        int row = wm * 32 + i * 16 + l15;
        aAddrH[i] = sbA + A_H_OFF + (uint32_t)(row * STRA_B) + hi16;
        aAddrL[i] = sbA + A_L_OFF + (uint32_t)(row * STRA_B) + hi16;
    }
    #pragma unroll
    for (int jp = 0; jp < 2; jp++)
        bOff[jp] = (uint32_t)((wn * 32 + jp * 16 + l15) * STRB_B) + hi16;

    float c[2][4][4];
    #pragma unroll
    for (int i = 0; i < 2; i++)
        #pragma unroll
        for (int j = 0; j < 4; j++)
            #pragma unroll
            for (int r = 0; r < 4; r++) c[i][j][r] = 0.f;

    float bd[2][2];
    int   bc[2][2];
    #pragma unroll
    for (int i = 0; i < 2; i++) { bd[i][0] = bd[i][1] = 3.4e38f; bc[i][0] = bc[i][1] = 0; }

    #pragma unroll 1
    for (int it = 0; it < NITER; it++) {
        int nt = it >> 3, kc = it & 7;
        int buf = it & 1;
        if (it + 1 < NITER) prefetch_chunk(it + 1, tid);
        CP_COMMIT();
        CP_WAIT1();
        __syncthreads();

        uint32_t bhBase = sbA + B_BASE + (uint32_t)(buf * B_BUF);
        uint32_t blBase = bhBase + B_HL;

        #pragma unroll
        for (int ks = 0; ks < 2; ks++) {
            uint32_t akb = (uint32_t)((kc * BK + ks * 16) * 2);   // A byte offset
            uint32_t bkb = (uint32_t)(ks * 32);                   // B byte offset
            uint32_t ah[2][4], al[2][4], bh[4][2], bl[4][2];

            #pragma unroll
            for (int i = 0; i < 2; i++)
                LDSM_X4(ah[i][0], ah[i][1], ah[i][2], ah[i][3], aAddrH[i] + akb);
            #pragma unroll
            for (int jp = 0; jp < 2; jp++)
                LDSM_X4(bh[2*jp][0], bh[2*jp+1][0], bh[2*jp][1], bh[2*jp+1][1],
                        bhBase + bOff[jp] + bkb);
            // pass 1: Ah * Bh
            #pragma unroll
            for (int i = 0; i < 2; i++)
                #pragma unroll
                for (int j = 0; j < 4; j++)
                    mma_bf16(c[i][j], ah[i][0], ah[i][1], ah[i][2], ah[i][3],
                             bh[j][0], bh[j][1]);
            // pass 2: Ah * Bl
            #pragma unroll
            for (int jp = 0; jp < 2; jp++)
                LDSM_X4(bl[2*jp][0], bl[2*jp+1][0], bl[2*jp][1], bl[2*jp+1][1],
                        blBase + bOff[jp] + bkb);
            #pragma unroll
            for (int i = 0; i < 2; i++)
                #pragma unroll
                for (int j = 0; j < 4; j++)
                    mma_bf16(c[i][j], ah[i][0], ah[i][1], ah[i][2], ah[i][3],
                             bl[j][0], bl[j][1]);
            // pass 3: Al * Bh
            #pragma unroll
            for (int i = 0; i < 2; i++)
                LDSM_X4(al[i][0], al[i][1], al[i][2], al[i][3], aAddrL[i] + akb);
            #pragma unroll
            for (int i = 0; i < 2; i++)
                #pragma unroll
                for (int j = 0; j < 4; j++)
                    mma_bf16(c[i][j], al[i][0], al[i][1], al[i][2], al[i][3],
                             bh[j][0], bh[j][1]);
        }

        if (kc == KCH - 1) {
            // fold tile nt into running per-row argmin; reset accumulators
            #pragma unroll
            for (int j = 0; j < 4; j++) {
                int col0 = nt * TILE_N + wn * 32 + j * 8 + 2 * t4;
                float e0 = __ldg(&g_enorm[col0]);
                float e1 = __ldg(&g_enorm[col0 + 1]);
                #pragma unroll
                for (int i = 0; i < 2; i++) {
                    float d0 = fmaf(-2.f, c[i][j][0], e0);
                    float d1 = fmaf(-2.f, c[i][j][1], e1);
                    float d2 = fmaf(-2.f, c[i][j][2], e0);
                    float d3 = fmaf(-2.f, c[i][j][3], e1);
                    if (d0 < bd[i][0] || (d0 == bd[i][0] && col0     < bc[i][0])) { bd[i][0] = d0; bc[i][0] = col0;     }
                    if (d1 < bd[i][0] || (d1 == bd[i][0] && col0 + 1 < bc[i][0])) { bd[i][0] = d1; bc[i][0] = col0 + 1; }
                    if (d2 < bd[i][1] || (d2 == bd[i][1] && col0     < bc[i][1])) { bd[i][1] = d2; bc[i][1] = col0;     }
                    if (d3 < bd[i][1] || (d3 == bd[i][1] && col0 + 1 < bc[i][1])) { bd[i][1] = d3; bc[i][1] = col0 + 1; }
                    c[i][j][0] = c[i][j][1] = c[i][j][2] = c[i][j][3] = 0.f;
                }
            }
        }
        __syncthreads();
    }

    // quad (t4) merge, lexicographic (d, c)
    #pragma unroll
    for (int i = 0; i < 2; i++)
        #pragma unroll
        for (int h = 0; h < 2; h++)
            #pragma unroll
            for (int sh = 1; sh <= 2; sh <<= 1) {
                float od = __shfl_xor_sync(0xffffffffu, bd[i][h], sh);
                int   oc = __shfl_xor_sync(0xffffffffu, bc[i][h], sh);
                if (od < bd[i][h] || (od == bd[i][h] && oc < bc[i][h])) {
                    bd[i][h] = od; bc[i][h] = oc;
                }
            }

    float* stD = (float*)(smem + STD);
    int*   stI = (int*)(smem + STI);
    if (t4 == 0) {
        #pragma unroll
        for (int i = 0; i < 2; i++)
            #pragma unroll
            for (int h = 0; h < 2; h++) {
                int row = wm * 32 + i * 16 + h * 8 + g;   // 0..63
                stD[row * 4 + wn] = bd[i][h];
                stI[row * 4 + wn] = bc[i][h];
            }
    }
    __syncthreads();
    if (tid < TILE_M) {
        float fb = stD[tid * 4];
        int   fc = stI[tid * 4];
        #pragma unroll
        for (int w = 1; w < 4; w++) {
            float d  = stD[tid * 4 + w];
            int   cc = stI[tid * 4 + w];
            if (d < fb || (d == fb && cc < fc)) { fb = d; fc = cc; }
        }
        g_idx[n0 + tid] = fc;
        atomicAdd(&g_hist[fc], 1u);
    }
}

// ---------------- kernel 3: coalesced gather + output + loss ---------------
__global__ __launch_bounds__(256)
void vq_gather_kernel(const float* __restrict__ z, const float* __restrict__ emb,
                      float* __restrict__ out) {
    __shared__ int   sidx[32];
    __shared__ float sE[32][257];
    int tid = threadIdx.x;
    int b   = blockIdx.x >> 7;
    int t0  = (blockIdx.x & 127) * 32;

    if (tid < 32) sidx[tid] = g_idx[b * ZT + t0 + tid];
    __syncthreads();

    {
        int r = tid >> 3;
        const float* row = emb + (size_t)sidx[r] * ZD;
        #pragma unroll
        for (int q = 0; q < 8; q++) {
            int c4 = (tid & 7) + q * 8;
            float4 v = *(const float4*)(row + c4 * 4);
            sE[r][c4 * 4 + 0] = v.x;
            sE[r][c4 * 4 + 1] = v.y;
            sE[r][c4 * 4 + 2] = v.z;
            sE[r][c4 * 4 + 3] = v.w;
        }
    }
    __syncthreads();

    float lsum = 0.f;
    int w = tid >> 5, lane = tid & 31;
    #pragma unroll 4
    for (int d = w; d < ZD; d += 8) {
        float e = sE[lane][d];
        size_t off = ((size_t)(b * ZD + d)) * ZT + t0 + lane;
        float zv = z[off];
        out[off] = e;
        float df = zv - e;
        lsum = fmaf(df, df, lsum);
    }

    __shared__ float ws[8];
    #pragma unroll
    for (int o = 16; o > 0; o >>= 1) lsum += __shfl_down_sync(0xffffffffu, lsum, o);
    if (lane == 0) ws[w] = lsum;
    __syncthreads();
    if (w == 0) {
        float s = (lane < 8) ? ws[lane] : 0.f;
        #pragma unroll
        for (int o = 4; o > 0; o >>= 1) s += __shfl_down_sync(0xffffffffu, s, o);
        if (lane == 0) atomicAdd(&g_loss, (double)s);
    }
}

// ---------------- kernel 4: perplexity + scalar outputs --------------------
__global__ void vq_finalize_kernel(float* __restrict__ out, int out_size) {
    __shared__ float warpsum[32];
    int t = threadIdx.x;
    float p = (float)g_hist[t] / (float)NVEC;
    float term = p * logf(p + 1e-10f);
    int lane = t & 31, w = t >> 5;
    #pragma unroll
    for (int o = 16; o > 0; o >>= 1) term += __shfl_down_sync(0xffffffffu, term, o);
    if (lane == 0) warpsum[w] = term;
    __syncthreads();
    if (w == 0) {
        float s = warpsum[lane];
        #pragma unroll
        for (int o = 16; o > 0; o >>= 1) s += __shfl_down_sync(0xffffffffu, s, o);
        if (lane == 0) {
            float perp = expf(-s);
            float loss = (float)g_loss;
            out[out_size - 3] = loss;
            out[out_size - 2] = loss;
            out[out_size - 1] = perp;
        }
    }
}

// ---------------- launcher -------------------------------------------------
extern "C" void kernel_launch(void* const* d_in, const int* in_sizes, int n_in,
                              void* d_out, int out_size) {
    const float* z   = (const float*)d_in[0];
    const float* emb = (const float*)d_in[1];
    if (n_in >= 2 && in_sizes[0] == NCODE * ZD && in_sizes[1] == NELEM) {
        const float* tmp = z; z = emb; emb = tmp;
    }
    float* out = (float*)d_out;

    cudaFuncSetAttribute(vq_argmin_3p,
                         cudaFuncAttributeMaxDynamicSharedMemorySize, SMEM_TOTAL);

    vq_embprep<<<NCODE, 256>>>(emb);
    vq_argmin_3p<<<NVEC / TILE_M, THREADS, SMEM_TOTAL>>>(z);
    vq_gather_kernel<<<ZB * (ZT / 32), 256>>>(z, emb, out);
    vq_finalize_kernel<<<1, 1024>>>(out, out_size);
}

// round 15
// speedup vs baseline: 1.2008x; 1.2008x over previous
#include <cuda_runtime.h>
#include <cuda_bf16.h>
#include <stdint.h>
#include <math.h>

#define ZB   16
#define ZD   256
#define ZT   4096
#define NVEC (ZB*ZT)            // 65536
#define NELEM (ZB*ZD*ZT)        // 16777216
#define NCODE 1024

#define TILE_M 64
#define TILE_N 128
#define BK     32
#define NT_TILES (NCODE/TILE_N)   // 8
#define KCH      (ZD/BK)          // 8
#define NITER    (NT_TILES*KCH)   // 64
#define THREADS  256

// A hi+lo: row stride 264 bf16 = 528 B
#define STRA_B 528
#define A_H_OFF 0
#define A_L_OFF (TILE_M*STRA_B)            // 33792
#define B_BASE (2*TILE_M*STRA_B)           // 67584
// per-warp B: 16 rows x 80B (64 used), hi+lo, double buffered
#define STRB_B 80
#define WB_HL   (16*STRB_B)                // 1280
#define WB_BUF  (2*WB_HL)                  // 2560
#define WB_WARP (2*WB_BUF)                 // 5120
#define SMEM_TOTAL (B_BASE + 8*WB_WARP)    // 108544
// epilogue scratch overlaps B region (B dead by then)
#define STD    B_BASE                      // [row][warp] float (64x8)
#define STI    (B_BASE + TILE_M*8*4)       // +2048

// ---------------- scratch --------------------------------------------------
__device__ __align__(16) __nv_bfloat16 g_eh[NCODE*ZD];
__device__ __align__(16) __nv_bfloat16 g_el[NCODE*ZD];
__device__ int           g_idx[NVEC];
__device__ unsigned int  g_hist[NCODE];
__device__ float         g_enorm[NCODE];
__device__ double        g_loss;

// ---------------- helpers --------------------------------------------------
__device__ __forceinline__ void mma_bf16(float c[4], uint32_t a0, uint32_t a1,
                                         uint32_t a2, uint32_t a3,
                                         uint32_t b0, uint32_t b1) {
    asm volatile(
        "mma.sync.aligned.m16n8k16.row.col.f32.bf16.bf16.f32 "
        "{%0,%1,%2,%3}, {%4,%5,%6,%7}, {%8,%9}, {%0,%1,%2,%3};"
        : "+f"(c[0]), "+f"(c[1]), "+f"(c[2]), "+f"(c[3])
        : "r"(a0), "r"(a1), "r"(a2), "r"(a3), "r"(b0), "r"(b1));
}
#define LDSM_X4(r0, r1, r2, r3, addr) \
    asm volatile("ldmatrix.sync.aligned.m8n8.x4.shared.b16 {%0,%1,%2,%3}, [%4];" \
        : "=r"(r0), "=r"(r1), "=r"(r2), "=r"(r3) : "r"(addr))
#define CP_ASYNC16(dst, src) \
    asm volatile("cp.async.cg.shared.global [%0], [%1], 16;" :: "r"(dst), "l"(src))
#define CP_COMMIT() asm volatile("cp.async.commit_group;" ::: "memory")
#define CP_WAIT1()  asm volatile("cp.async.wait_group 1;" ::: "memory")

__device__ __forceinline__ uint32_t smem_u32(const void* p) {
    uint32_t a;
    asm("{ .reg .u64 t; cvta.to.shared.u64 t, %1; cvt.u32.u64 %0, t; }" : "=r"(a) : "l"(p));
    return a;
}

// ---------------- kernel 1: init + codebook prep ---------------------------
__global__ __launch_bounds__(256) void vq_embprep(const float* __restrict__ emb) {
    int c = blockIdx.x, d = threadIdx.x;
    if (d == 0) {
        g_hist[c] = 0u;
        if (c == 0) g_loss = 0.0;
    }
    float v = emb[(size_t)c * ZD + d];
    __nv_bfloat16 h = __float2bfloat16_rn(v);
    float hf = __bfloat162float(h);
    g_eh[(size_t)c * ZD + d] = h;
    g_el[(size_t)c * ZD + d] = __float2bfloat16_rn(v - hf);

    float sv = v * v;
    __shared__ float wv[8];
    int lane = d & 31, w = d >> 5;
    #pragma unroll
    for (int o = 16; o > 0; o >>= 1) sv += __shfl_down_sync(0xffffffffu, sv, o);
    if (lane == 0) wv[w] = sv;
    __syncthreads();
    if (d == 0) {
        float tv = 0.f;
        #pragma unroll
        for (int i = 0; i < 8; i++) tv += wv[i];
        g_enorm[c] = tv;
    }
}

// ---------------- kernel 2: 3-pass HMMA exact argmin, warp-private B -------
extern __shared__ char smem[];

// each warp loads its own 16 code rows (hi+lo) for chunk it2
__device__ __forceinline__ void warp_prefetch(int it2, uint32_t wbase, int lane,
                                              const __nv_bfloat16* ehw,
                                              const __nv_bfloat16* elw) {
    int kc = it2 & 7, buf = it2 & 1;
    size_t ntOff = (size_t)((it2 >> 3) * TILE_N) * ZD + kc * BK;
    #pragma unroll
    for (int q = 0; q < 4; q++) {
        int idx = lane + q * 32;            // 0..127
        int hl  = idx >> 6;                 // 0:hi 1:lo
        int rem = idx & 63;
        int row = rem >> 2;                 // 0..15 warp-local code row
        int seg = rem & 3;
        const __nv_bfloat16* src =
            (hl ? elw : ehw) + (ntOff + (size_t)row * ZD + seg * 8);
        uint32_t dst = wbase + buf * WB_BUF + hl * WB_HL + row * STRB_B + seg * 16;
        CP_ASYNC16(dst, src);
    }
}

__global__ __launch_bounds__(THREADS, 2)
void vq_argmin_3p(const float* __restrict__ z) {
    int tid = threadIdx.x, lane = tid & 31, wid = tid >> 5;
    int g = lane >> 2, t4 = lane & 3;
    int l15 = lane & 15;
    uint32_t hi16 = (lane & 16) ? 16u : 0u;

    int n0 = blockIdx.x * TILE_M;
    int b  = n0 / ZT, t0 = n0 % ZT;
    const float* zb = z + (size_t)b * ZD * ZT + t0;
    uint32_t sbA = smem_u32(smem);
    uint32_t wbase = sbA + B_BASE + wid * WB_WARP;
    const __nv_bfloat16* ehw = g_eh + (size_t)wid * 16 * ZD;
    const __nv_bfloat16* elw = g_el + (size_t)wid * 16 * ZD;

    // A tile: hi + lo split (64 rows x 256 dims), shared by all warps
    {
        int r = tid & 63;
        #pragma unroll 1
        for (int itl = 0; itl < 8; itl++) {
            int kq = (tid >> 6) + itl * 4;       // 0..31
            union { __nv_bfloat16 h[8]; uint4 u; } H, L;
            #pragma unroll
            for (int j = 0; j < 8; j++) {
                float v = zb[(size_t)(kq * 8 + j) * ZT + r];
                __nv_bfloat16 hh = __float2bfloat16_rn(v);
                H.h[j] = hh;
                L.h[j] = __float2bfloat16_rn(v - __bfloat162float(hh));
            }
            uint32_t off = (uint32_t)(r * STRA_B + kq * 16);
            *(uint4*)(smem + A_H_OFF + off) = H.u;
            *(uint4*)(smem + A_L_OFF + off) = L.u;
        }
    }

    warp_prefetch(0, wbase, lane, ehw, elw);
    CP_COMMIT();
    __syncthreads();   // A visible to all warps; B pipelines are warp-private

    // ldmatrix lane addresses (loop-invariant parts)
    uint32_t aAddrH[4], aAddrL[4];
    #pragma unroll
    for (int i = 0; i < 4; i++) {
        int row = i * 16 + l15;
        aAddrH[i] = sbA + A_H_OFF + (uint32_t)(row * STRA_B) + hi16;
        aAddrL[i] = sbA + A_L_OFF + (uint32_t)(row * STRA_B) + hi16;
    }
    uint32_t bOffW = (uint32_t)(l15 * STRB_B) + hi16;

    float c[4][2][4];
    #pragma unroll
    for (int i = 0; i < 4; i++)
        #pragma unroll
        for (int j = 0; j < 2; j++)
            #pragma unroll
            for (int r = 0; r < 4; r++) c[i][j][r] = 0.f;

    float bd[4][2];
    int   bc[4][2];
    #pragma unroll
    for (int i = 0; i < 4; i++) { bd[i][0] = bd[i][1] = 3.4e38f; bc[i][0] = bc[i][1] = 0; }

    #pragma unroll 1
    for (int it = 0; it < NITER; it++) {
        int nt = it >> 3, kc = it & 7;
        int buf = it & 1;
        if (it + 1 < NITER) warp_prefetch(it + 1, wbase, lane, ehw, elw);
        CP_COMMIT();
        CP_WAIT1();
        __syncwarp();

        uint32_t bhBase = wbase + (uint32_t)(buf * WB_BUF);
        uint32_t blBase = bhBase + WB_HL;

        #pragma unroll
        for (int ks = 0; ks < 2; ks++) {
            uint32_t akb = (uint32_t)((kc * BK + ks * 16) * 2);   // A byte offset
            uint32_t bkb = (uint32_t)(ks * 32);                   // B byte offset
            uint32_t ah[4][4], al[4][4], bh[2][2], bl[2][2];

            #pragma unroll
            for (int i = 0; i < 4; i++)
                LDSM_X4(ah[i][0], ah[i][1], ah[i][2], ah[i][3], aAddrH[i] + akb);
            LDSM_X4(bh[0][0], bh[1][0], bh[0][1], bh[1][1], bhBase + bOffW + bkb);
            // pass 1: Ah * Bh
            #pragma unroll
            for (int i = 0; i < 4; i++)
                #pragma unroll
                for (int j = 0; j < 2; j++)
                    mma_bf16(c[i][j], ah[i][0], ah[i][1], ah[i][2], ah[i][3],
                             bh[j][0], bh[j][1]);
            // pass 2: Ah * Bl
            LDSM_X4(bl[0][0], bl[1][0], bl[0][1], bl[1][1], blBase + bOffW + bkb);
            #pragma unroll
            for (int i = 0; i < 4; i++)
                #pragma unroll
                for (int j = 0; j < 2; j++)
                    mma_bf16(c[i][j], ah[i][0], ah[i][1], ah[i][2], ah[i][3],
                             bl[j][0], bl[j][1]);
            // pass 3: Al * Bh
            #pragma unroll
            for (int i = 0; i < 4; i++)
                LDSM_X4(al[i][0], al[i][1], al[i][2], al[i][3], aAddrL[i] + akb);
            #pragma unroll
            for (int i = 0; i < 4; i++)
                #pragma unroll
                for (int j = 0; j < 2; j++)
                    mma_bf16(c[i][j], al[i][0], al[i][1], al[i][2], al[i][3],
                             bh[j][0], bh[j][1]);
        }

        if (kc == KCH - 1) {
            // fold tile nt into running per-row argmin; reset accumulators
            #pragma unroll
            for (int j = 0; j < 2; j++) {
                int col0 = nt * TILE_N + wid * 16 + j * 8 + 2 * t4;
                float e0 = __ldg(&g_enorm[col0]);
                float e1 = __ldg(&g_enorm[col0 + 1]);
                #pragma unroll
                for (int i = 0; i < 4; i++) {
                    float d0 = fmaf(-2.f, c[i][j][0], e0);
                    float d1 = fmaf(-2.f, c[i][j][1], e1);
                    float d2 = fmaf(-2.f, c[i][j][2], e0);
                    float d3 = fmaf(-2.f, c[i][j][3], e1);
                    if (d0 < bd[i][0] || (d0 == bd[i][0] && col0     < bc[i][0])) { bd[i][0] = d0; bc[i][0] = col0;     }
                    if (d1 < bd[i][0] || (d1 == bd[i][0] && col0 + 1 < bc[i][0])) { bd[i][0] = d1; bc[i][0] = col0 + 1; }
                    if (d2 < bd[i][1] || (d2 == bd[i][1] && col0     < bc[i][1])) { bd[i][1] = d2; bc[i][1] = col0;     }
                    if (d3 < bd[i][1] || (d3 == bd[i][1] && col0 + 1 < bc[i][1])) { bd[i][1] = d3; bc[i][1] = col0 + 1; }
                    c[i][j][0] = c[i][j][1] = c[i][j][2] = c[i][j][3] = 0.f;
                }
            }
        }
    }

    // quad (t4) merge, lexicographic (d, c)
    #pragma unroll
    for (int i = 0; i < 4; i++)
        #pragma unroll
        for (int h = 0; h < 2; h++)
            #pragma unroll
            for (int sh = 1; sh <= 2; sh <<= 1) {
                float od = __shfl_xor_sync(0xffffffffu, bd[i][h], sh);
                int   oc = __shfl_xor_sync(0xffffffffu, bc[i][h], sh);
                if (od < bd[i][h] || (od == bd[i][h] && oc < bc[i][h])) {
                    bd[i][h] = od; bc[i][h] = oc;
                }
            }

    __syncthreads();   // all warps done with B region; reuse as scratch
    float* stD = (float*)(smem + STD);
    int*   stI = (int*)(smem + STI);
    if (t4 == 0) {
        #pragma unroll
        for (int i = 0; i < 4; i++)
            #pragma unroll
            for (int h = 0; h < 2; h++) {
                int row = i * 16 + h * 8 + g;     // 0..63
                stD[row * 8 + wid] = bd[i][h];
                stI[row * 8 + wid] = bc[i][h];
            }
    }
    __syncthreads();
    if (tid < TILE_M) {
        float fb = stD[tid * 8];
        int   fc = stI[tid * 8];
        #pragma unroll
        for (int w = 1; w < 8; w++) {
            float d  = stD[tid * 8 + w];
            int   cc = stI[tid * 8 + w];
            if (d < fb || (d == fb && cc < fc)) { fb = d; fc = cc; }
        }
        g_idx[n0 + tid] = fc;
        atomicAdd(&g_hist[fc], 1u);
    }
}

// ---------------- kernel 3: coalesced gather + output + loss ---------------
__global__ __launch_bounds__(256)
void vq_gather_kernel(const float* __restrict__ z, const float* __restrict__ emb,
                      float* __restrict__ out) {
    __shared__ int   sidx[32];
    __shared__ float sE[32][257];
    int tid = threadIdx.x;
    int b   = blockIdx.x >> 7;
    int t0  = (blockIdx.x & 127) * 32;

    if (tid < 32) sidx[tid] = g_idx[b * ZT + t0 + tid];
    __syncthreads();

    {
        int r = tid >> 3;
        const float* row = emb + (size_t)sidx[r] * ZD;
        #pragma unroll
        for (int q = 0; q < 8; q++) {
            int c4 = (tid & 7) + q * 8;
            float4 v = *(const float4*)(row + c4 * 4);
            sE[r][c4 * 4 + 0] = v.x;
            sE[r][c4 * 4 + 1] = v.y;
            sE[r][c4 * 4 + 2] = v.z;
            sE[r][c4 * 4 + 3] = v.w;
        }
    }
    __syncthreads();

    float lsum = 0.f;
    int w = tid >> 5, lane = tid & 31;
    #pragma unroll 4
    for (int d = w; d < ZD; d += 8) {
        float e = sE[lane][d];
        size_t off = ((size_t)(b * ZD + d)) * ZT + t0 + lane;
        float zv = z[off];
        out[off] = e;
        float df = zv - e;
        lsum = fmaf(df, df, lsum);
    }

    __shared__ float ws[8];
    #pragma unroll
    for (int o = 16; o > 0; o >>= 1) lsum += __shfl_down_sync(0xffffffffu, lsum, o);
    if (lane == 0) ws[w] = lsum;
    __syncthreads();
    if (w == 0) {
        float s = (lane < 8) ? ws[lane] : 0.f;
        #pragma unroll
        for (int o = 4; o > 0; o >>= 1) s += __shfl_down_sync(0xffffffffu, s, o);
        if (lane == 0) atomicAdd(&g_loss, (double)s);
    }
}

// ---------------- kernel 4: perplexity + scalar outputs --------------------
__global__ void vq_finalize_kernel(float* __restrict__ out, int out_size) {
    __shared__ float warpsum[32];
    int t = threadIdx.x;
    float p = (float)g_hist[t] / (float)NVEC;
    float term = p * logf(p + 1e-10f);
    int lane = t & 31, w = t >> 5;
    #pragma unroll
    for (int o = 16; o > 0; o >>= 1) term += __shfl_down_sync(0xffffffffu, term, o);
    if (lane == 0) warpsum[w] = term;
    __syncthreads();
    if (w == 0) {
        float s = warpsum[lane];
        #pragma unroll
        for (int o = 16; o > 0; o >>= 1) s += __shfl_down_sync(0xffffffffu, s, o);
        if (lane == 0) {
            float perp = expf(-s);
            float loss = (float)g_loss;
            out[out_size - 3] = loss;
            out[out_size - 2] = loss;
            out[out_size - 1] = perp;
        }
    }
}

// ---------------- launcher -------------------------------------------------
extern "C" void kernel_launch(void* const* d_in, const int* in_sizes, int n_in,
                              void* d_out, int out_size) {
    const float* z   = (const float*)d_in[0];
    const float* emb = (const float*)d_in[1];
    if (n_in >= 2 && in_sizes[0] == NCODE * ZD && in_sizes[1] == NELEM) {
        const float* tmp = z; z = emb; emb = tmp;
    }
    float* out = (float*)d_out;

    cudaFuncSetAttribute(vq_argmin_3p,
                         cudaFuncAttributeMaxDynamicSharedMemorySize, SMEM_TOTAL);

    vq_embprep<<<NCODE, 256>>>(emb);
    vq_argmin_3p<<<NVEC / TILE_M, THREADS, SMEM_TOTAL>>>(z);
    vq_gather_kernel<<<ZB * (ZT / 32), 256>>>(z, emb, out);
    vq_finalize_kernel<<<1, 1024>>>(out, out_size);
}